// round 1
// baseline (speedup 1.0000x reference)
#include <cuda_runtime.h>
#include <math.h>

#define Bv   64
#define Cv   64
#define COv  64
#define Nv   400
#define Lv   24
#define NNv  160000
#define NLv  9600
#define CLv  1536          // CO*L
#define PER_B 614400       // CO*N*L
#define OUT_S_OFF 39321600
#define OUT_T_OFF 49561600

// ---------------- persistent scratch (device globals; no allocation) -------
__device__ float g_xinput[39321600];   // [b][o][n][l]
__device__ float g_f1t[614400];        // [b][l][n]
__device__ float g_f2t[98304];         // [b][c][l]  (atomic accum -> zeroed)
__device__ float g_f1s[614400];        // [b][n][l]
__device__ float g_f2s[1638400];       // [b][c][n]
__device__ float g_g1s[1638400];       // [b][n][c]
__device__ float g_slog[10240000];     // [b][n][m]
__device__ float g_sl2[10240000];      // [b][p][n]
__device__ float g_colmax[25600];      // [b][n]
__device__ float g_xt2[39321600];      // [b][n][c][l]
__device__ float g_Y[117964800];       // [b][k][n][o*L]
__device__ float g_gcn[39321600];      // [b][n][o*L]
__device__ float g_h[39321600];        // [b][o][n][l]
__device__ float g_Tch[320000];        // [2][N][N] : T1=adj, T2=2adj^2-I
__device__ double g_stats[128];        // [b]{sum,sumsq}

// ---------------- K-zero: clear atomic accumulators ------------------------
__global__ void zero_kernel() {
    int i = blockIdx.x * 256 + threadIdx.x;
    if (i < 98304) g_f2t[i] = 0.f;
    if (i < 128)   g_stats[i] = 0.0;
}

// ---------------- Chebyshev polys T1, T2 -----------------------------------
__global__ void cheb_kernel(const float* __restrict__ adj) {
    int n = blockIdx.x * 128 + threadIdx.x;
    int q = blockIdx.y;
    if (n >= Nv) return;
    g_Tch[q * Nv + n] = adj[q * Nv + n];
    float s = 0.f;
    for (int m = 0; m < Nv; m++) s += adj[q * Nv + m] * adj[m * Nv + n];
    g_Tch[NNv + q * Nv + n] = 2.f * s - (q == n ? 1.f : 0.f);
}

// ---------------- fused attention feature reductions (one pass over x) -----
__global__ __launch_bounds__(256) void feat_kernel(
    const float* __restrict__ x, const float* __restrict__ tcw1,
    const float* __restrict__ tcw2, const float* __restrict__ scw1,
    const float* __restrict__ scw2) {
    int b = blockIdx.y;
    int n0 = blockIdx.x * 40;
    __shared__ float sx[960];
    __shared__ float a_t[960];   // sum_c tcw1[c]*x  (idx = nl*24+l)
    __shared__ float a_s[960];   // sum_c scw1[c]*x
    int tid = threadIdx.x;
    for (int i = tid; i < 960; i += 256) { a_t[i] = 0.f; a_s[i] = 0.f; }
    __syncthreads();
    for (int c = 0; c < Cv; c++) {
        const float* xp = x + ((size_t)(b * Cv + c)) * NLv + n0 * Lv;
        for (int i = tid; i < 960; i += 256) sx[i] = xp[i];
        __syncthreads();
        float w1t = tcw1[c], w1s = scw1[c];
        for (int i = tid; i < 960; i += 256) {
            float v = sx[i];
            a_t[i] += w1t * v;
            a_s[i] += w1s * v;
        }
        if (tid < 40) {   // f2s[b,c,n] = sum_l scw2[l]*x[n,l]
            float s = 0.f;
            for (int l = 0; l < Lv; l++) s += scw2[l] * sx[tid * Lv + l];
            g_f2s[(b * Cv + c) * Nv + n0 + tid] = s;
        }
        if (tid >= 64 && tid < 64 + Lv) {  // f2t partial
            int l = tid - 64;
            float s = 0.f;
            for (int j = 0; j < 40; j++) s += tcw2[n0 + j] * sx[j * Lv + l];
            atomicAdd(&g_f2t[(b * Cv + c) * Lv + l], s);
        }
        __syncthreads();
    }
    for (int i = tid; i < 960; i += 256) {
        int nl = i / Lv, l = i % Lv;
        g_f1t[(b * Lv + l) * Nv + n0 + nl] = a_t[i];
        g_f1s[(b * Nv + n0 + nl) * Lv + l] = a_s[i];
    }
}

// ---------------- conv1: x_input = W @ x + b  ([b]: 64x64 @ 64x9600) ------
__global__ __launch_bounds__(256) void conv1_kernel(
    const float* __restrict__ x, const float* __restrict__ w,
    const float* __restrict__ bias) {
    int b = blockIdx.y, j0 = blockIdx.x * 64;
    __shared__ float Ws[64][64];   // [c][o]
    __shared__ float Bs[16][64];
    int tid = threadIdx.x;
    for (int i = tid; i < 4096; i += 256) { int o = i / 64, c = i % 64; Ws[c][o] = w[i]; }
    float acc[4][4] = {};
    int tx = tid % 16, ty = tid / 16;
    for (int k0 = 0; k0 < 64; k0 += 16) {
        __syncthreads();
        for (int i = tid; i < 1024; i += 256) {
            int kk = i / 64, jj = i % 64;
            Bs[kk][jj] = x[(size_t)(b * 64 + k0 + kk) * NLv + j0 + jj];
        }
        __syncthreads();
#pragma unroll
        for (int kk = 0; kk < 16; kk++) {
            float4 a = *(float4*)&Ws[k0 + kk][ty * 4];
            float4 bb = *(float4*)&Bs[kk][tx * 4];
            float av[4] = {a.x, a.y, a.z, a.w}, bvv[4] = {bb.x, bb.y, bb.z, bb.w};
#pragma unroll
            for (int i = 0; i < 4; i++)
#pragma unroll
                for (int j = 0; j < 4; j++) acc[i][j] += av[i] * bvv[j];
        }
    }
#pragma unroll
    for (int i = 0; i < 4; i++) {
        int o = ty * 4 + i;
        float bo = bias[o];
#pragma unroll
        for (int j = 0; j < 4; j++)
            g_xinput[(size_t)(b * 64 + o) * NLv + j0 + tx * 4 + j] = acc[i][j] + bo;
    }
}

// ---------------- temporal attention (one block per batch) -----------------
__global__ __launch_bounds__(256) void tatt_kernel(
    const float* __restrict__ tw, const float* __restrict__ tb,
    const float* __restrict__ tv, float* __restrict__ out_T) {
    int b = blockIdx.x;
    __shared__ float sf2[Cv * Lv];
    __shared__ float sg1[Lv * Cv];
    __shared__ float stl[Lv * Lv];
    __shared__ float stl2[Lv * Lv];
    __shared__ float scmax[Lv];
    int tid = threadIdx.x;
    for (int i = tid; i < Cv * Lv; i += 256) sf2[i] = g_f2t[b * Cv * Lv + i];
    __syncthreads();
    const float* f1 = &g_f1t[b * Lv * Nv];
    for (int i = tid; i < Lv * Cv; i += 256) {     // g1[l,c] = f1[l,:] . tw[:,c]
        int l = i / Cv, c = i % Cv;
        float s = 0.f;
        for (int n = 0; n < Nv; n++) s += f1[l * Nv + n] * tw[n * Cv + c];
        sg1[i] = s;
    }
    __syncthreads();
    for (int i = tid; i < Lv * Lv; i += 256) {     // sigmoid(g1 @ f2 + tb)
        int l = i / Lv, m = i % Lv;
        float s = 0.f;
        for (int c = 0; c < Cv; c++) s += sg1[l * Cv + c] * sf2[c * Lv + m];
        s += tb[i];
        stl[i] = 1.f / (1.f + expf(-s));
    }
    __syncthreads();
    for (int i = tid; i < Lv * Lv; i += 256) {     // tv @ stl
        int p = i / Lv, l = i % Lv;
        float s = 0.f;
        for (int q = 0; q < Lv; q++) s += tv[p * Lv + q] * stl[q * Lv + l];
        stl2[i] = s;
    }
    __syncthreads();
    if (tid < Lv) {                                // col max over p
        float m = -1e30f;
        for (int p = 0; p < Lv; p++) m = fmaxf(m, stl2[p * Lv + tid]);
        scmax[tid] = m;
    }
    __syncthreads();
    if (tid < Lv) {                                // row softmax over l
        int p = tid;
        float z[Lv], rm = -1e30f;
        for (int l = 0; l < Lv; l++) { z[l] = stl2[p * Lv + l] - scmax[l]; rm = fmaxf(rm, z[l]); }
        float s = 0.f, e[Lv];
        for (int l = 0; l < Lv; l++) { e[l] = expf(z[l] - rm); s += e[l]; }
        float inv = 1.f / s;
        // returned T_coef is TRANSPOSED: Tt[b,l,p] = P[p,l]
        for (int l = 0; l < Lv; l++) out_T[b * Lv * Lv + l * Lv + p] = e[l] * inv;
    }
}

// ---------------- spatial attention ----------------------------------------
__global__ __launch_bounds__(256) void g1s_kernel(const float* __restrict__ sw) {
    __shared__ float ssw[Lv * Cv];
    int tid = threadIdx.x;
    for (int i = tid; i < Lv * Cv; i += 256) ssw[i] = sw[i];
    __syncthreads();
    int idx = blockIdx.x * 256 + tid;           // over B*N*C
    int c = idx % Cv, bn = idx / Cv;
    const float* f1 = &g_f1s[bn * Lv];
    float s = 0.f;
    for (int l = 0; l < Lv; l++) s += f1[l] * ssw[l * Cv + c];
    g_g1s[idx] = s;
}

__global__ __launch_bounds__(256) void slog_kernel(const float* __restrict__ sb) {
    int b = blockIdx.y, n0 = blockIdx.x * 4;
    __shared__ float sg[4 * Cv];
    int tid = threadIdx.x;
    for (int i = tid; i < 4 * Cv; i += 256) sg[i] = g_g1s[(b * Nv + n0) * Cv + i];
    __syncthreads();
    for (int m = tid; m < Nv; m += 256) {
        float a0 = 0, a1 = 0, a2 = 0, a3 = 0;
        for (int c = 0; c < Cv; c++) {
            float f = g_f2s[(b * Cv + c) * Nv + m];
            a0 += sg[c] * f; a1 += sg[Cv + c] * f;
            a2 += sg[2 * Cv + c] * f; a3 += sg[3 * Cv + c] * f;
        }
        a0 += sb[(n0 + 0) * Nv + m]; a1 += sb[(n0 + 1) * Nv + m];
        a2 += sb[(n0 + 2) * Nv + m]; a3 += sb[(n0 + 3) * Nv + m];
        g_slog[(b * Nv + n0 + 0) * Nv + m] = 1.f / (1.f + expf(-a0));
        g_slog[(b * Nv + n0 + 1) * Nv + m] = 1.f / (1.f + expf(-a1));
        g_slog[(b * Nv + n0 + 2) * Nv + m] = 1.f / (1.f + expf(-a2));
        g_slog[(b * Nv + n0 + 3) * Nv + m] = 1.f / (1.f + expf(-a3));
    }
}

// sl2[b,p,n] = sum_q s_v[p,q] * slog[b,q,n]
__global__ __launch_bounds__(256) void sv_gemm_kernel(const float* __restrict__ sv) {
    int b = blockIdx.z, p0 = blockIdx.y * 64, n0 = blockIdx.x * 64;
    __shared__ float As[16][64];   // [kk][pp]
    __shared__ float Bs[16][64];
    float acc[4][4] = {};
    int tid = threadIdx.x, tx = tid % 16, ty = tid / 16;
    for (int k0 = 0; k0 < Nv; k0 += 16) {
        __syncthreads();
        for (int i = tid; i < 1024; i += 256) {
            int pp = i / 16, kk = i % 16, p = p0 + pp;
            As[kk][pp] = (p < Nv) ? sv[p * Nv + k0 + kk] : 0.f;
        }
        for (int i = tid; i < 1024; i += 256) {
            int kk = i / 64, nn = i % 64;
            Bs[kk][nn] = (n0 + nn < Nv) ? g_slog[(b * Nv + k0 + kk) * Nv + n0 + nn] : 0.f;
        }
        __syncthreads();
#pragma unroll
        for (int kk = 0; kk < 16; kk++) {
            float4 a = *(float4*)&As[kk][ty * 4];
            float4 bb = *(float4*)&Bs[kk][tx * 4];
            float av[4] = {a.x, a.y, a.z, a.w}, bvv[4] = {bb.x, bb.y, bb.z, bb.w};
#pragma unroll
            for (int i = 0; i < 4; i++)
#pragma unroll
                for (int j = 0; j < 4; j++) acc[i][j] += av[i] * bvv[j];
        }
    }
#pragma unroll
    for (int i = 0; i < 4; i++) {
        int p = p0 + ty * 4 + i;
        if (p >= Nv) continue;
#pragma unroll
        for (int j = 0; j < 4; j++) {
            int n = n0 + tx * 4 + j;
            if (n < Nv) g_sl2[(b * Nv + p) * Nv + n] = acc[i][j];
        }
    }
}

__global__ void colmax_kernel() {
    int b = blockIdx.x;
    for (int n = threadIdx.x; n < Nv; n += blockDim.x) {
        float m = -1e30f;
        for (int p = 0; p < Nv; p++) m = fmaxf(m, g_sl2[(b * Nv + p) * Nv + n]);
        g_colmax[b * Nv + n] = m;
    }
}

__global__ __launch_bounds__(128) void s_softmax_kernel(float* __restrict__ outS) {
    int b = blockIdx.y, p = blockIdx.x;
    __shared__ float buf[Nv];
    __shared__ float red[128];
    int tid = threadIdx.x;
    float lm = -1e30f;
    for (int n = tid; n < Nv; n += 128) {
        float z = g_sl2[(b * Nv + p) * Nv + n] - g_colmax[b * Nv + n];
        buf[n] = z;
        lm = fmaxf(lm, z);
    }
    red[tid] = lm; __syncthreads();
    for (int st = 64; st > 0; st >>= 1) { if (tid < st) red[tid] = fmaxf(red[tid], red[tid + st]); __syncthreads(); }
    float M = red[0];
    __syncthreads();
    float s = 0.f;
    for (int n = tid; n < Nv; n += 128) { float e = expf(buf[n] - M); buf[n] = e; s += e; }
    red[tid] = s; __syncthreads();
    for (int st = 64; st > 0; st >>= 1) { if (tid < st) red[tid] += red[tid + st]; __syncthreads(); }
    float inv = 1.f / red[0];
    for (int n = tid; n < Nv; n += 128) outS[(b * Nv + p) * Nv + n] = buf[n] * inv;
}

// ---------------- x_TAt, stored transposed: XT2[b,n,c,l] -------------------
__global__ __launch_bounds__(256) void xtat_kernel(
    const float* __restrict__ x, const float* __restrict__ Tt) {
    int b = blockIdx.y, n = blockIdx.x;
    __shared__ float sT[Lv * Lv];
    __shared__ float sx[8][Lv];
    int tid = threadIdx.x;
    for (int i = tid; i < Lv * Lv; i += 256) sT[i] = Tt[b * Lv * Lv + i];
    __syncthreads();
    int g = tid / 32, lane = tid % 32;
    for (int c = g; c < Cv; c += 8) {
        if (lane < Lv) sx[g][lane] = x[((size_t)(b * Cv + c) * Nv + n) * Lv + lane];
        __syncwarp();
        if (lane < Lv) {
            float s = 0.f;
#pragma unroll
            for (int lp = 0; lp < Lv; lp++) s += sx[g][lp] * sT[lp * Lv + lane];
            g_xt2[((size_t)(b * Nv + n) * Cv + c) * Lv + lane] = s;
        }
        __syncwarp();
    }
}

// ---------------- Y[b,k,n,o,l] = sum_c g_w[o, c*3+k] * XT2[b,n,c,l] --------
__global__ __launch_bounds__(256) void ygemm_kernel(const float* __restrict__ gw) {
    int b = blockIdx.y, n0 = blockIdx.x * 4;
    __shared__ float sx[4 * 64 * 24];
    __shared__ float swk[64 * 64];   // [c][o]
    int tid = threadIdx.x;
    for (int i = tid; i < 6144; i += 256) sx[i] = g_xt2[(size_t)(b * Nv + n0) * Cv * Lv + i];
    int nl = tid / 64, rr = tid % 64, og = rr / 4, lh = rr % 4;
    for (int k = 0; k < 3; k++) {
        __syncthreads();
        for (int i = tid; i < 4096; i += 256) {
            int o = i / 64, c = i % 64;
            swk[c * 64 + o] = gw[o * 192 + c * 3 + k];
        }
        __syncthreads();
        float acc[4][6] = {};
#pragma unroll 4
        for (int c = 0; c < 64; c++) {
            float4 w4 = *(float4*)&swk[c * 64 + og * 4];
            const float* xs = &sx[(nl * 64 + c) * Lv + lh * 6];
            float wv[4] = {w4.x, w4.y, w4.z, w4.w};
            float xv[6] = {xs[0], xs[1], xs[2], xs[3], xs[4], xs[5]};
#pragma unroll
            for (int a = 0; a < 4; a++)
#pragma unroll
                for (int e = 0; e < 6; e++) acc[a][e] += wv[a] * xv[e];
        }
        float* yp = &g_Y[((size_t)(b * 3 + k) * Nv + n0 + nl) * CLv];
#pragma unroll
        for (int a = 0; a < 4; a++)
#pragma unroll
            for (int e = 0; e < 6; e++) yp[(og * 4 + a) * Lv + lh * 6 + e] = acc[a][e];
    }
}

// ---------------- main GCN GEMM: gcn = relu(diag + sum_k (S.*T_k) @ Y_k + g_b)
__global__ __launch_bounds__(256) void gcn_gemm_kernel(
    const float* __restrict__ Sc, const float* __restrict__ gb) {
    int b = blockIdx.z, q0 = blockIdx.y * 128, j0 = blockIdx.x * 64;
    __shared__ float As[16][128];
    __shared__ float Bs[16][64];
    float acc[8][4] = {};
    int tid = threadIdx.x, tx = tid % 16, ty = tid / 16;
    const float* Sb = Sc + (size_t)b * NNv;
    for (int kc = 1; kc <= 2; kc++) {
        const float* Tc = g_Tch + (size_t)(kc - 1) * NNv;
        const float* Yb = g_Y + (size_t)(b * 3 + kc) * Nv * CLv;
        for (int n0 = 0; n0 < Nv; n0 += 16) {
            __syncthreads();
            for (int i = tid; i < 2048; i += 256) {
                int qq = i / 16, kk = i % 16, q = q0 + qq;
                As[kk][qq] = (q < Nv) ? Sb[q * Nv + n0 + kk] * Tc[q * Nv + n0 + kk] : 0.f;
            }
            for (int i = tid; i < 1024; i += 256) {
                int kk = i / 64, jj = i % 64;
                Bs[kk][jj] = Yb[(size_t)(n0 + kk) * CLv + j0 + jj];
            }
            __syncthreads();
#pragma unroll
            for (int kk = 0; kk < 16; kk++) {
                float4 a0 = *(float4*)&As[kk][ty * 8];
                float4 a1 = *(float4*)&As[kk][ty * 8 + 4];
                float4 b4 = *(float4*)&Bs[kk][tx * 4];
                float av[8] = {a0.x, a0.y, a0.z, a0.w, a1.x, a1.y, a1.z, a1.w};
                float bv[4] = {b4.x, b4.y, b4.z, b4.w};
#pragma unroll
                for (int i = 0; i < 8; i++)
#pragma unroll
                    for (int j = 0; j < 4; j++) acc[i][j] += av[i] * bv[j];
            }
        }
    }
    const float* Y0 = g_Y + (size_t)(b * 3) * Nv * CLv;
#pragma unroll
    for (int i = 0; i < 8; i++) {
        int q = q0 + ty * 8 + i;
        if (q >= Nv) continue;
        float sd = Sb[q * Nv + q];
#pragma unroll
        for (int j = 0; j < 4; j++) {
            int jj = j0 + tx * 4 + j;
            float v = acc[i][j] + sd * Y0[(size_t)q * CLv + jj] + gb[jj / Lv];
            g_gcn[(size_t)(b * Nv + q) * CLv + jj] = fmaxf(v, 0.f);
        }
    }
}

// ---------------- temporal conv + residual + relu + LN stats ---------------
#define TCONV_SMEM ((12288 + 6656) * 4)
__global__ __launch_bounds__(256) void tconv_kernel(
    const float* __restrict__ tw, const float* __restrict__ tcb) {
    extern __shared__ float sh[];
    float* sw = sh;                 // [i][t][o] : 12288
    float* sg = sh + 12288;         // [nl][i][26] halo : 6656
    int b = blockIdx.y, n0 = blockIdx.x * 4;
    int tid = threadIdx.x;
    for (int i = tid; i < 12288; i += 256) {
        int o = i / 192, r = i % 192, ic = r / 3, t = r % 3;
        sw[(ic * 3 + t) * 64 + o] = tw[(o * 64 + ic) * 3 + t];
    }
    for (int idx = tid; idx < 6656; idx += 256) {
        int nl = idx / (64 * 26), r = idx % (64 * 26), ic = r / 26, ll = r % 26;
        int l = ll - 1;
        sg[idx] = (l >= 0 && l < Lv)
                      ? g_gcn[((size_t)(b * Nv + n0 + nl) * 64 + ic) * Lv + l] : 0.f;
    }
    __syncthreads();
    int nl = tid / 64, rr = tid % 64, og = rr / 4, lh = rr % 4;
    float acc[4][6] = {};
#pragma unroll 4
    for (int ic = 0; ic < 64; ic++) {
        const float* gp = &sg[(nl * 64 + ic) * 26 + lh * 6];
        float xv[8];
#pragma unroll
        for (int u = 0; u < 8; u++) xv[u] = gp[u];
#pragma unroll
        for (int t = 0; t < 3; t++) {
            float4 w4 = *(float4*)&sw[(ic * 3 + t) * 64 + og * 4];
            float wv[4] = {w4.x, w4.y, w4.z, w4.w};
#pragma unroll
            for (int a = 0; a < 4; a++)
#pragma unroll
                for (int e = 0; e < 6; e++) acc[a][e] += wv[a] * xv[e + t];
        }
    }
    __syncthreads();
    float* sout = sh + 12288;       // reuse: [o][nl*24+l] : 6144
#pragma unroll
    for (int a = 0; a < 4; a++)
#pragma unroll
        for (int e = 0; e < 6; e++)
            sout[(og * 4 + a) * 96 + nl * Lv + lh * 6 + e] = acc[a][e];
    __syncthreads();
    double lsum = 0.0, lsq = 0.0;
    for (int i = tid; i < 6144; i += 256) {
        int o = i / 96, r = i % 96;
        size_t gidx = (size_t)(b * 64 + o) * NLv + n0 * Lv + r;
        float v = sout[i] + tcb[o] + g_xinput[gidx];
        v = fmaxf(v, 0.f);
        g_h[gidx] = v;
        lsum += v; lsq += (double)v * v;
    }
    __shared__ double rs[256], rq[256];
    rs[tid] = lsum; rq[tid] = lsq; __syncthreads();
    for (int st = 128; st > 0; st >>= 1) {
        if (tid < st) { rs[tid] += rs[tid + st]; rq[tid] += rq[tid + st]; }
        __syncthreads();
    }
    if (tid == 0) {
        atomicAdd(&g_stats[b * 2], rs[0]);
        atomicAdd(&g_stats[b * 2 + 1], rq[0]);
    }
}

// ---------------- layernorm apply ------------------------------------------
__global__ __launch_bounds__(256) void ln_kernel(
    const float* __restrict__ lng, const float* __restrict__ lnb,
    float* __restrict__ out) {
    int b = blockIdx.y;
    int r = blockIdx.x * 256 + threadIdx.x;       // 0..614399
    double s1 = g_stats[b * 2], s2 = g_stats[b * 2 + 1];
    double mud = s1 / (double)PER_B;
    float mu = (float)mud;
    float var = (float)(s2 / (double)PER_B - mud * mud);
    float rstd = rsqrtf(var + 1e-5f);
    size_t idx = (size_t)b * PER_B + r;
    float h = g_h[idx];
    out[idx] = (h - mu) * rstd * lng[r] + lnb[r];
}

// ---------------- launch ---------------------------------------------------
extern "C" void kernel_launch(void* const* d_in, const int* in_sizes, int n_in,
                              void* d_out, int out_size) {
    const float* x       = (const float*)d_in[0];
    const float* adj     = (const float*)d_in[1];
    const float* conv1_w = (const float*)d_in[2];
    const float* conv1_b = (const float*)d_in[3];
    const float* t_cw1   = (const float*)d_in[4];
    const float* t_cw2   = (const float*)d_in[5];
    const float* t_w     = (const float*)d_in[6];
    const float* t_b     = (const float*)d_in[7];
    const float* t_v     = (const float*)d_in[8];
    const float* s_cw1   = (const float*)d_in[9];
    const float* s_cw2   = (const float*)d_in[10];
    const float* s_w     = (const float*)d_in[11];
    const float* s_b     = (const float*)d_in[12];
    const float* s_v     = (const float*)d_in[13];
    const float* g_wp    = (const float*)d_in[14];
    const float* g_bp    = (const float*)d_in[15];
    const float* tc_wp   = (const float*)d_in[16];
    const float* tc_bp   = (const float*)d_in[17];
    const float* ln_gp   = (const float*)d_in[18];
    const float* ln_bp   = (const float*)d_in[19];
    float* out  = (float*)d_out;
    float* outS = out + OUT_S_OFF;
    float* outT = out + OUT_T_OFF;

    zero_kernel<<<384, 256>>>();
    cheb_kernel<<<dim3(4, Nv), 128>>>(adj);
    feat_kernel<<<dim3(10, Bv), 256>>>(x, t_cw1, t_cw2, s_cw1, s_cw2);
    conv1_kernel<<<dim3(150, Bv), 256>>>(x, conv1_w, conv1_b);
    tatt_kernel<<<Bv, 256>>>(t_w, t_b, t_v, outT);
    g1s_kernel<<<6400, 256>>>(s_w);
    slog_kernel<<<dim3(100, Bv), 256>>>(s_b);
    sv_gemm_kernel<<<dim3(7, 7, Bv), 256>>>(s_v);
    colmax_kernel<<<Bv, 512>>>();
    s_softmax_kernel<<<dim3(Nv, Bv), 128>>>(outS);
    xtat_kernel<<<dim3(Nv, Bv), 256>>>(x, outT);
    ygemm_kernel<<<dim3(100, Bv), 256>>>(g_wp);
    gcn_gemm_kernel<<<dim3(24, 4, Bv), 256>>>(outS, g_bp);
    cudaFuncSetAttribute(tconv_kernel, cudaFuncAttributeMaxDynamicSharedMemorySize, TCONV_SMEM);
    tconv_kernel<<<dim3(100, Bv), 256, TCONV_SMEM>>>(tc_wp, tc_bp);
    ln_kernel<<<dim3(2400, Bv), 256>>>(ln_gp, ln_bp, out);
}

// round 3
// speedup vs baseline: 1.3162x; 1.3162x over previous
#include <cuda_runtime.h>
#include <math.h>

#define Bv   64
#define Cv   64
#define COv  64
#define Nv   400
#define Lv   24
#define NNv  160000
#define NLv  9600
#define CLv  1536          // CO*L
#define PER_B 614400       // CO*N*L
#define OUT_S_OFF 39321600
#define OUT_T_OFF 49561600

// ---------------- persistent scratch (device globals; no allocation) -------
__device__ float g_xinput[39321600];   // [b][o][n][l]
__device__ float g_f1t[614400];        // [b][l][n]
__device__ float g_f2t[98304];         // [b][c][l]  (atomic accum -> zeroed)
__device__ float g_f1s[614400];        // [b][n][l]
__device__ float g_f2s[1638400];       // [b][c][n]
__device__ float g_g1s[1638400];       // [b][n][c]
__device__ float g_slog[10240000];     // [b][n][m]
__device__ float g_sl2[10240000];      // [b][p][n]
__device__ float g_colmax[102400];     // [4][b][n] partial col max
__device__ float g_xt[39321600];       // [b][c][n][l]  x_TAt natural layout
__device__ float g_Y[117964800];       // [b][k][n][o*L]
__device__ float g_gcn[39321600];      // [b][n][o*L]
__device__ float g_h[39321600];        // [b][o][n][l]
__device__ float g_Tch[320000];        // [2][N][N] : T1=adj, T2=2adj^2-I
__device__ double g_stats[128];        // [b]{sum,sumsq}

// ---------------- zero atomic accumulators ---------------------------------
__global__ void zero_kernel() {
    int i = blockIdx.x * 256 + threadIdx.x;
    if (i < 98304) g_f2t[i] = 0.f;
    if (i < 128)   g_stats[i] = 0.0;
}

// ---------------- Chebyshev polys T1, T2 -----------------------------------
__global__ void cheb_kernel(const float* __restrict__ adj) {
    int n = blockIdx.x * 128 + threadIdx.x;
    int q = blockIdx.y;
    if (n >= Nv) return;
    g_Tch[q * Nv + n] = adj[q * Nv + n];
    float s = 0.f;
    for (int m = 0; m < Nv; m++) s += adj[q * Nv + m] * adj[m * Nv + n];
    g_Tch[NNv + q * Nv + n] = 2.f * s - (q == n ? 1.f : 0.f);
}

// ---------------- fused attention feature reductions -----------------------
__global__ __launch_bounds__(256) void feat_kernel(
    const float* __restrict__ x, const float* __restrict__ tcw1,
    const float* __restrict__ tcw2, const float* __restrict__ scw1,
    const float* __restrict__ scw2) {
    int b = blockIdx.y;
    int n0 = blockIdx.x * 40;
    __shared__ float sx[960];
    __shared__ float a_t[960];
    __shared__ float a_s[960];
    int tid = threadIdx.x;
    for (int i = tid; i < 960; i += 256) { a_t[i] = 0.f; a_s[i] = 0.f; }
    __syncthreads();
    for (int c = 0; c < Cv; c++) {
        const float* xp = x + ((size_t)(b * Cv + c)) * NLv + n0 * Lv;
        for (int i = tid; i < 960; i += 256) sx[i] = xp[i];
        __syncthreads();
        float w1t = tcw1[c], w1s = scw1[c];
        for (int i = tid; i < 960; i += 256) {
            float v = sx[i];
            a_t[i] += w1t * v;
            a_s[i] += w1s * v;
        }
        if (tid < 40) {
            float s = 0.f;
            for (int l = 0; l < Lv; l++) s += scw2[l] * sx[tid * Lv + l];
            g_f2s[(b * Cv + c) * Nv + n0 + tid] = s;
        }
        if (tid >= 64 && tid < 64 + Lv) {
            int l = tid - 64;
            float s = 0.f;
            for (int j = 0; j < 40; j++) s += tcw2[n0 + j] * sx[j * Lv + l];
            atomicAdd(&g_f2t[(b * Cv + c) * Lv + l], s);
        }
        __syncthreads();
    }
    for (int i = tid; i < 960; i += 256) {
        int nl = i / Lv, l = i % Lv;
        g_f1t[(b * Lv + l) * Nv + n0 + nl] = a_t[i];
        g_f1s[(b * Nv + n0 + nl) * Lv + l] = a_s[i];
    }
}

// ---------------- conv1: GEMM 64x9600x64 per b, 8x8 micro ------------------
__global__ __launch_bounds__(128) void conv1_kernel(
    const float* __restrict__ x, const float* __restrict__ w,
    const float* __restrict__ bias) {
    int b = blockIdx.y, j0 = blockIdx.x * 128;
    __shared__ float Ws[64][64];   // [c][o]
    __shared__ float Bs[16][128];
    int tid = threadIdx.x;
    for (int i = tid; i < 4096; i += 128) { int o = i >> 6, c = i & 63; Ws[c][o] = w[i]; }
    float acc[8][8] = {};
    int tx = tid & 15, ty = tid >> 4;
    for (int k0 = 0; k0 < 64; k0 += 16) {
        __syncthreads();
#pragma unroll
        for (int v = 0; v < 4; v++) {
            int f = v * 128 + tid;
            int kk = f >> 5, jj = (f & 31) * 4;
            *(float4*)&Bs[kk][jj] =
                *(const float4*)&x[(size_t)(b * 64 + k0 + kk) * NLv + j0 + jj];
        }
        __syncthreads();
#pragma unroll
        for (int kk = 0; kk < 16; kk++) {
            float4 a0 = *(float4*)&Ws[k0 + kk][ty * 8];
            float4 a1 = *(float4*)&Ws[k0 + kk][ty * 8 + 4];
            float4 b0 = *(float4*)&Bs[kk][tx * 8];
            float4 b1 = *(float4*)&Bs[kk][tx * 8 + 4];
            float av[8] = {a0.x,a0.y,a0.z,a0.w,a1.x,a1.y,a1.z,a1.w};
            float bv[8] = {b0.x,b0.y,b0.z,b0.w,b1.x,b1.y,b1.z,b1.w};
#pragma unroll
            for (int i = 0; i < 8; i++)
#pragma unroll
                for (int j = 0; j < 8; j++) acc[i][j] += av[i] * bv[j];
        }
    }
#pragma unroll
    for (int i = 0; i < 8; i++) {
        int o = ty * 8 + i;
        float bo = bias[o];
        float* op = &g_xinput[(size_t)(b * 64 + o) * NLv + j0 + tx * 8];
#pragma unroll
        for (int j = 0; j < 8; j++) op[j] = acc[i][j] + bo;
    }
}

// ---------------- temporal attention ---------------------------------------
__global__ __launch_bounds__(256) void tatt_kernel(
    const float* __restrict__ tw, const float* __restrict__ tb,
    const float* __restrict__ tv, float* __restrict__ out_T) {
    int b = blockIdx.x;
    __shared__ float sf2[Cv * Lv];
    __shared__ float sg1[Lv * Cv];
    __shared__ float stl[Lv * Lv];
    __shared__ float stl2[Lv * Lv];
    __shared__ float scmax[Lv];
    int tid = threadIdx.x;
    for (int i = tid; i < Cv * Lv; i += 256) sf2[i] = g_f2t[b * Cv * Lv + i];
    __syncthreads();
    const float* f1 = &g_f1t[b * Lv * Nv];
    for (int i = tid; i < Lv * Cv; i += 256) {
        int l = i / Cv, c = i % Cv;
        float s = 0.f;
        for (int n = 0; n < Nv; n++) s += f1[l * Nv + n] * tw[n * Cv + c];
        sg1[i] = s;
    }
    __syncthreads();
    for (int i = tid; i < Lv * Lv; i += 256) {
        int l = i / Lv, m = i % Lv;
        float s = 0.f;
        for (int c = 0; c < Cv; c++) s += sg1[l * Cv + c] * sf2[c * Lv + m];
        s += tb[i];
        stl[i] = 1.f / (1.f + expf(-s));
    }
    __syncthreads();
    for (int i = tid; i < Lv * Lv; i += 256) {
        int p = i / Lv, l = i % Lv;
        float s = 0.f;
        for (int q = 0; q < Lv; q++) s += tv[p * Lv + q] * stl[q * Lv + l];
        stl2[i] = s;
    }
    __syncthreads();
    if (tid < Lv) {
        float m = -1e30f;
        for (int p = 0; p < Lv; p++) m = fmaxf(m, stl2[p * Lv + tid]);
        scmax[tid] = m;
    }
    __syncthreads();
    if (tid < Lv) {
        int p = tid;
        float z[Lv], rm = -1e30f;
        for (int l = 0; l < Lv; l++) { z[l] = stl2[p * Lv + l] - scmax[l]; rm = fmaxf(rm, z[l]); }
        float s = 0.f, e[Lv];
        for (int l = 0; l < Lv; l++) { e[l] = expf(z[l] - rm); s += e[l]; }
        float inv = 1.f / s;
        for (int l = 0; l < Lv; l++) out_T[b * Lv * Lv + l * Lv + p] = e[l] * inv;
    }
}

// ---------------- spatial attention ----------------------------------------
__global__ __launch_bounds__(256) void g1s_kernel(const float* __restrict__ sw) {
    __shared__ float ssw[Lv * Cv];
    int tid = threadIdx.x;
    for (int i = tid; i < Lv * Cv; i += 256) ssw[i] = sw[i];
    __syncthreads();
    int idx = blockIdx.x * 256 + tid;
    int c = idx & 63, bn = idx >> 6;
    const float* f1 = &g_f1s[bn * Lv];
    float s = 0.f;
    for (int l = 0; l < Lv; l++) s += f1[l] * ssw[l * Cv + c];
    g_g1s[idx] = s;
}

// slog[b,n,m] = sigmoid(g1s[b,n,:] . f2s[b,:,m] + sb[n,m]); 16-n tiles
__global__ __launch_bounds__(128) void slog_kernel(const float* __restrict__ sb) {
    int b = blockIdx.y, n0 = blockIdx.x * 16;
    __shared__ float sg[64 * 17];
    int tid = threadIdx.x;
#pragma unroll
    for (int v = 0; v < 8; v++) {
        int idx = v * 128 + tid;
        int c = idx & 63, r = idx >> 6;
        sg[c * 17 + r] = g_g1s[(size_t)(b * Nv + n0 + r) * 64 + c];
    }
    __syncthreads();
    int m = tid * 4;
    if (m < Nv) {
        float acc[16][4] = {};
        for (int c = 0; c < 64; c++) {
            float4 f = *(const float4*)&g_f2s[(size_t)(b * 64 + c) * Nv + m];
            float fv[4] = {f.x, f.y, f.z, f.w};
#pragma unroll
            for (int r = 0; r < 16; r++) {
                float w = sg[c * 17 + r];
#pragma unroll
                for (int u = 0; u < 4; u++) acc[r][u] += w * fv[u];
            }
        }
#pragma unroll
        for (int r = 0; r < 16; r++) {
#pragma unroll
            for (int u = 0; u < 4; u++) {
                float a = acc[r][u] + sb[(n0 + r) * Nv + m + u];
                g_slog[(size_t)(b * Nv + n0 + r) * Nv + m + u] = 1.f / (1.f + expf(-a));
            }
        }
    }
}

// sl2[b,p,n] = sum_q s_v[p,q]*slog[b,q,n]; 80x80 tiles, 5x5 micro
__global__ __launch_bounds__(256) void sv_gemm_kernel(const float* __restrict__ sv) {
    int b = blockIdx.z, p0 = blockIdx.y * 80, n0 = blockIdx.x * 80;
    __shared__ float As[16][81];
    __shared__ float Bs[16][81];
    float acc[5][5] = {};
    int tid = threadIdx.x, tx = tid & 15, ty = tid >> 4;
    for (int k0 = 0; k0 < Nv; k0 += 16) {
        __syncthreads();
#pragma unroll
        for (int v = 0; v < 5; v++) {
            int idx = v * 256 + tid;
            int pp = idx >> 4, kk = idx & 15;
            As[kk][pp] = sv[(p0 + pp) * Nv + k0 + kk];
        }
#pragma unroll
        for (int v = 0; v < 5; v++) {
            int idx = v * 256 + tid;
            int kk = idx / 80, nn = idx % 80;
            Bs[kk][nn] = g_slog[(size_t)(b * Nv + k0 + kk) * Nv + n0 + nn];
        }
        __syncthreads();
#pragma unroll
        for (int kk = 0; kk < 16; kk++) {
            float av[5], bv[5];
#pragma unroll
            for (int i = 0; i < 5; i++) av[i] = As[kk][ty * 5 + i];
#pragma unroll
            for (int j = 0; j < 5; j++) bv[j] = Bs[kk][tx * 5 + j];
#pragma unroll
            for (int i = 0; i < 5; i++)
#pragma unroll
                for (int j = 0; j < 5; j++) acc[i][j] += av[i] * bv[j];
        }
    }
#pragma unroll
    for (int i = 0; i < 5; i++)
#pragma unroll
        for (int j = 0; j < 5; j++)
            g_sl2[(size_t)(b * Nv + p0 + ty * 5 + i) * Nv + n0 + tx * 5 + j] = acc[i][j];
}

// partial column max over p in 4 chunks, coalesced
__global__ __launch_bounds__(512) void colmax_kernel() {
    int u = blockIdx.x, b = blockIdx.y;
    int n = threadIdx.x;
    if (n >= Nv) return;
    float m = -1e30f;
    int p0 = u * 100;
    for (int p = p0; p < p0 + 100; p++)
        m = fmaxf(m, g_sl2[((size_t)b * Nv + p) * Nv + n]);
    g_colmax[(u * Bv + b) * Nv + n] = m;
}

__global__ __launch_bounds__(128) void s_softmax_kernel(float* __restrict__ outS) {
    int b = blockIdx.y, p = blockIdx.x;
    __shared__ float buf[Nv];
    __shared__ float red[128];
    int tid = threadIdx.x;
    float lm = -1e30f;
    for (int n = tid; n < Nv; n += 128) {
        float cm = fmaxf(fmaxf(g_colmax[(0 * Bv + b) * Nv + n], g_colmax[(1 * Bv + b) * Nv + n]),
                         fmaxf(g_colmax[(2 * Bv + b) * Nv + n], g_colmax[(3 * Bv + b) * Nv + n]));
        float z = g_sl2[((size_t)b * Nv + p) * Nv + n] - cm;
        buf[n] = z;
        lm = fmaxf(lm, z);
    }
    red[tid] = lm; __syncthreads();
    for (int st = 64; st > 0; st >>= 1) { if (tid < st) red[tid] = fmaxf(red[tid], red[tid + st]); __syncthreads(); }
    float M = red[0];
    __syncthreads();
    float s = 0.f;
    for (int n = tid; n < Nv; n += 128) { float e = expf(buf[n] - M); buf[n] = e; s += e; }
    red[tid] = s; __syncthreads();
    for (int st = 64; st > 0; st >>= 1) { if (tid < st) red[tid] += red[tid + st]; __syncthreads(); }
    float inv = 1.f / red[0];
    for (int n = tid; n < Nv; n += 128) outS[((size_t)b * Nv + p) * Nv + n] = buf[n] * inv;
}

// ---------------- x_TAt natural layout: xt[b,c,n,q] = sum_l x[.,l]*P[q,l] --
__global__ __launch_bounds__(256) void xt_kernel(
    const float* __restrict__ x, const float* __restrict__ Tt) {
    int b = blockIdx.y, r0 = blockIdx.x * 64;   // rows over c*400+n
    __shared__ float sT[576];
    __shared__ float sx[64 * 24];
    int tid = threadIdx.x;
    for (int i = tid; i < 576; i += 256) sT[i] = Tt[b * 576 + i];
    const float* xb = x + ((size_t)b * 25600 + r0) * 24;
    for (int i = tid; i < 1536; i += 256) sx[i] = xb[i];
    __syncthreads();
    int row = tid >> 2, lh = (tid & 3) * 6;
    float out[6] = {};
    const float* xr = &sx[row * 24];
#pragma unroll
    for (int lp = 0; lp < 24; lp++) {
        float v = xr[lp];
#pragma unroll
        for (int e = 0; e < 6; e++) out[e] += v * sT[lp * 24 + lh + e];
    }
    float* yp = &g_xt[((size_t)b * 25600 + r0 + row) * 24 + lh];
#pragma unroll
    for (int e = 0; e < 6; e++) yp[e] = out[e];
}

// ---------------- Y_k = W_k @ x_TAt : GEMM 64x9600x64, store [n][(o,l)] ----
__global__ __launch_bounds__(128) void ygemm_kernel(const float* __restrict__ gw) {
    int by = blockIdx.y;
    int b = by / 3, kc = by % 3;
    int j0 = blockIdx.x * 128;
    __shared__ float Ws[64][64];   // [c][o]
    __shared__ float Bs[16][128];
    int tid = threadIdx.x;
    for (int i = tid; i < 4096; i += 128) {
        int o = i >> 6, c = i & 63;
        Ws[c][o] = gw[o * 192 + c * 3 + kc];
    }
    float acc[8][8] = {};
    int tx = tid & 15, ty = tid >> 4;
    const float* xb = g_xt + (size_t)b * PER_B;
    for (int k0 = 0; k0 < 64; k0 += 16) {
        __syncthreads();
#pragma unroll
        for (int v = 0; v < 4; v++) {
            int f = v * 128 + tid;
            int kk = f >> 5, jj = (f & 31) * 4;
            *(float4*)&Bs[kk][jj] = *(const float4*)&xb[(size_t)(k0 + kk) * NLv + j0 + jj];
        }
        __syncthreads();
#pragma unroll
        for (int kk = 0; kk < 16; kk++) {
            float4 a0 = *(float4*)&Ws[k0 + kk][ty * 8];
            float4 a1 = *(float4*)&Ws[k0 + kk][ty * 8 + 4];
            float4 b0 = *(float4*)&Bs[kk][tx * 8];
            float4 b1 = *(float4*)&Bs[kk][tx * 8 + 4];
            float av[8] = {a0.x,a0.y,a0.z,a0.w,a1.x,a1.y,a1.z,a1.w};
            float bv[8] = {b0.x,b0.y,b0.z,b0.w,b1.x,b1.y,b1.z,b1.w};
#pragma unroll
            for (int i = 0; i < 8; i++)
#pragma unroll
                for (int j = 0; j < 8; j++) acc[i][j] += av[i] * bv[j];
        }
    }
    float* Yb = g_Y + (size_t)by * Nv * CLv;
#pragma unroll
    for (int i = 0; i < 8; i++) {
        int o = ty * 8 + i;
#pragma unroll
        for (int j = 0; j < 8; j++) {
            int jg = j0 + tx * 8 + j;
            int n = jg / 24, l = jg - n * 24;
            Yb[(size_t)n * CLv + o * 24 + l] = acc[i][j];
        }
    }
}

// ---------------- main GCN GEMM: 80(q)x128(j), K=2x400, 5x8 micro ----------
__global__ __launch_bounds__(256) void gcn_gemm_kernel(
    const float* __restrict__ Sc, const float* __restrict__ gb) {
    int b = blockIdx.z, q0 = blockIdx.y * 80, j0 = blockIdx.x * 128;
    __shared__ float As[16][81];
    __shared__ float Bs[16][128];
    float acc[5][8] = {};
    int tid = threadIdx.x, tx = tid & 15, ty = tid >> 4;
    const float* Sb = Sc + (size_t)b * NNv;
    for (int kc = 1; kc <= 2; kc++) {
        const float* Tc = g_Tch + (size_t)(kc - 1) * NNv;
        const float* Yb = g_Y + (size_t)(b * 3 + kc) * Nv * CLv;
        for (int n0 = 0; n0 < Nv; n0 += 16) {
            __syncthreads();
#pragma unroll
            for (int v = 0; v < 5; v++) {
                int idx = v * 256 + tid;
                int qq = idx >> 4, kk = idx & 15;
                int q = q0 + qq, n = n0 + kk;
                As[kk][qq] = Sb[q * Nv + n] * Tc[q * Nv + n];
            }
#pragma unroll
            for (int v = 0; v < 2; v++) {
                int f = v * 256 + tid;
                int kk = f >> 5, jj = (f & 31) * 4;
                *(float4*)&Bs[kk][jj] =
                    *(const float4*)&Yb[(size_t)(n0 + kk) * CLv + j0 + jj];
            }
            __syncthreads();
#pragma unroll
            for (int kk = 0; kk < 16; kk++) {
                float av[5];
#pragma unroll
                for (int i = 0; i < 5; i++) av[i] = As[kk][ty * 5 + i];
                float4 b0 = *(float4*)&Bs[kk][tx * 8];
                float4 b1 = *(float4*)&Bs[kk][tx * 8 + 4];
                float bv[8] = {b0.x,b0.y,b0.z,b0.w,b1.x,b1.y,b1.z,b1.w};
#pragma unroll
                for (int i = 0; i < 5; i++)
#pragma unroll
                    for (int j = 0; j < 8; j++) acc[i][j] += av[i] * bv[j];
            }
        }
    }
    const float* Y0 = g_Y + (size_t)(b * 3) * Nv * CLv;
#pragma unroll
    for (int i = 0; i < 5; i++) {
        int q = q0 + ty * 5 + i;
        float sd = Sb[q * Nv + q];
#pragma unroll
        for (int j = 0; j < 8; j++) {
            int jg = j0 + tx * 8 + j;
            float v = acc[i][j] + sd * Y0[(size_t)q * CLv + jg] + gb[jg / 24];
            g_gcn[((size_t)b * Nv + q) * CLv + jg] = fmaxf(v, 0.f);
        }
    }
}

// ---------------- temporal conv + residual + relu + LN stats ---------------
#define TCONV_SMEM (25600 * 4)
__global__ __launch_bounds__(256) void tconv_kernel(
    const float* __restrict__ tw, const float* __restrict__ tcb) {
    extern __shared__ float sh[];
    float* sw = sh;              // [(ic*3+t)*64+o] : 12288
    float* sg = sh + 12288;      // [nl][ic][26]    : 13312
    int b = blockIdx.y, n0 = blockIdx.x * 8;
    int tid = threadIdx.x;
    for (int i = tid; i < 12288; i += 256) {
        int o = i / 192, r = i % 192, ic = r / 3, t = r % 3;
        sw[(ic * 3 + t) * 64 + o] = tw[(o * 64 + ic) * 3 + t];
    }
    for (int idx = tid; idx < 13312; idx += 256) {
        int nl = idx / 1664, r = idx % 1664, ic = r / 26, ll = r % 26;
        int l = ll - 1;
        sg[idx] = (l >= 0 && l < Lv)
                      ? g_gcn[((size_t)(b * Nv + n0 + nl) * 64 + ic) * Lv + l] : 0.f;
    }
    __syncthreads();
    int lh = tid & 3, og = (tid >> 2) & 7, nl = tid >> 5;
    float acc[8][6] = {};
    for (int ic = 0; ic < 64; ic++) {
        const float* gp = &sg[(nl * 64 + ic) * 26 + lh * 6];
        float xv[8];
#pragma unroll
        for (int u = 0; u < 8; u++) xv[u] = gp[u];
#pragma unroll
        for (int t = 0; t < 3; t++) {
            const float* wp = &sw[(ic * 3 + t) * 64 + og * 8];
            float4 w0 = *(const float4*)wp, w1 = *(const float4*)(wp + 4);
            float wv[8] = {w0.x,w0.y,w0.z,w0.w,w1.x,w1.y,w1.z,w1.w};
#pragma unroll
            for (int a = 0; a < 8; a++)
#pragma unroll
                for (int e = 0; e < 6; e++) acc[a][e] += wv[a] * xv[e + t];
        }
    }
    __syncthreads();
    float* sout = sh;            // reuse sw region: [o][nl*24+l] : 12288
#pragma unroll
    for (int a = 0; a < 8; a++)
#pragma unroll
        for (int e = 0; e < 6; e++)
            sout[(og * 8 + a) * 192 + nl * Lv + lh * 6 + e] = acc[a][e];
    __syncthreads();
    double lsum = 0.0, lsq = 0.0;
    for (int i = tid; i < 12288; i += 256) {
        int o = i / 192, r = i % 192;
        size_t gidx = (size_t)(b * 64 + o) * NLv + n0 * Lv + r;
        float v = sout[i] + tcb[o] + g_xinput[gidx];
        v = fmaxf(v, 0.f);
        g_h[gidx] = v;
        lsum += v; lsq += (double)v * v;
    }
    __shared__ double rs[256], rq[256];
    rs[tid] = lsum; rq[tid] = lsq; __syncthreads();
    for (int st = 128; st > 0; st >>= 1) {
        if (tid < st) { rs[tid] += rs[tid + st]; rq[tid] += rq[tid + st]; }
        __syncthreads();
    }
    if (tid == 0) {
        atomicAdd(&g_stats[b * 2], rs[0]);
        atomicAdd(&g_stats[b * 2 + 1], rq[0]);
    }
}

// ---------------- layernorm apply ------------------------------------------
__global__ __launch_bounds__(256) void ln_kernel(
    const float* __restrict__ lng, const float* __restrict__ lnb,
    float* __restrict__ out) {
    int b = blockIdx.y;
    int r = blockIdx.x * 256 + threadIdx.x;
    double s1 = g_stats[b * 2], s2 = g_stats[b * 2 + 1];
    double mud = s1 / (double)PER_B;
    float mu = (float)mud;
    float var = (float)(s2 / (double)PER_B - mud * mud);
    float rstd = rsqrtf(var + 1e-5f);
    size_t idx = (size_t)b * PER_B + r;
    float h = g_h[idx];
    out[idx] = (h - mu) * rstd * lng[r] + lnb[r];
}

// ---------------- launch ---------------------------------------------------
extern "C" void kernel_launch(void* const* d_in, const int* in_sizes, int n_in,
                              void* d_out, int out_size) {
    const float* x       = (const float*)d_in[0];
    const float* adj     = (const float*)d_in[1];
    const float* conv1_w = (const float*)d_in[2];
    const float* conv1_b = (const float*)d_in[3];
    const float* t_cw1   = (const float*)d_in[4];
    const float* t_cw2   = (const float*)d_in[5];
    const float* t_w     = (const float*)d_in[6];
    const float* t_b     = (const float*)d_in[7];
    const float* t_v     = (const float*)d_in[8];
    const float* s_cw1   = (const float*)d_in[9];
    const float* s_cw2   = (const float*)d_in[10];
    const float* s_w     = (const float*)d_in[11];
    const float* s_b     = (const float*)d_in[12];
    const float* s_v     = (const float*)d_in[13];
    const float* g_wp    = (const float*)d_in[14];
    const float* g_bp    = (const float*)d_in[15];
    const float* tc_wp   = (const float*)d_in[16];
    const float* tc_bp   = (const float*)d_in[17];
    const float* ln_gp   = (const float*)d_in[18];
    const float* ln_bp   = (const float*)d_in[19];
    float* out  = (float*)d_out;
    float* outS = out + OUT_S_OFF;
    float* outT = out + OUT_T_OFF;

    zero_kernel<<<384, 256>>>();
    cheb_kernel<<<dim3(4, Nv), 128>>>(adj);
    feat_kernel<<<dim3(10, Bv), 256>>>(x, t_cw1, t_cw2, s_cw1, s_cw2);
    conv1_kernel<<<dim3(75, Bv), 128>>>(x, conv1_w, conv1_b);
    tatt_kernel<<<Bv, 256>>>(t_w, t_b, t_v, outT);
    g1s_kernel<<<6400, 256>>>(s_w);
    slog_kernel<<<dim3(25, Bv), 128>>>(s_b);
    sv_gemm_kernel<<<dim3(5, 5, Bv), 256>>>(s_v);
    colmax_kernel<<<dim3(4, Bv), 512>>>();
    s_softmax_kernel<<<dim3(Nv, Bv), 128>>>(outS);
    xt_kernel<<<dim3(400, Bv), 256>>>(x, outT);
    ygemm_kernel<<<dim3(75, Bv * 3), 128>>>(g_wp);
    gcn_gemm_kernel<<<dim3(12, 5, Bv), 256>>>(outS, g_bp);
    cudaFuncSetAttribute(tconv_kernel, cudaFuncAttributeMaxDynamicSharedMemorySize, TCONV_SMEM);
    tconv_kernel<<<dim3(50, Bv), 256, TCONV_SMEM>>>(tc_wp, tc_bp);
    ln_kernel<<<dim3(2400, Bv), 256>>>(ln_gp, ln_bp, out);
}